// round 17
// baseline (speedup 1.0000x reference)
#include <cuda_runtime.h>
#include <cuda_bf16.h>
#include <cuda_fp8.h>
#include <cstdint>

#define B_TOK 8192
#define D_IN  2048
#define N_LAT 16384
#define K_TOP 32
#define CAND_MIN 48
#define CAND_CAP 640
#define SEL_MARGIN 0.3f
#define WIN_EPS 2e-5
#define CMP_TAU 2e-7    // INVERTED routing: |gap| <= tau => exact decides; |gap| > tau => serial
#define WIN_CAP 16

#define SCALE_X 4.0f
#define SCALE_W 32.0f
#define INV_SCALE (1.0f / (SCALE_X * SCALE_W))
#define D2 (D_IN / 2)   // k-dim in fp8-pair (16-bit) units

// ---------------- scratch (device globals; no allocs allowed) ----------------
__device__ uint16_t g_x8[(size_t)B_TOK * D2];           //  16 MB  e4m3 pairs of (x-b_dec)*4
__device__ uint16_t g_w8[(size_t)N_LAT * D2];           //  32 MB  e4m3 pairs of W_enc*32
__device__ __nv_bfloat16 g_pre[(size_t)B_TOK * N_LAT];  // 256 MB  approx pre-acts

// ---------------- conversion kernels ----------------
__device__ __forceinline__ uint16_t f2e4m3(float a, float b) {
    return (uint16_t)__nv_cvt_float2_to_fp8x2(make_float2(a, b), __NV_SATFINITE, __NV_E4M3);
}

__global__ void conv_x_kernel(const float* __restrict__ x, const float* __restrict__ bdec) {
    size_t i = ((size_t)blockIdx.x * 256 + threadIdx.x) * 8;
    if (i >= (size_t)B_TOK * D_IN) return;
    int col = (int)(i & (D_IN - 1));
    float4 x0 = *(const float4*)(x + i);
    float4 x1 = *(const float4*)(x + i + 4);
    float4 b0 = *(const float4*)(bdec + col);
    float4 b1 = *(const float4*)(bdec + col + 4);
    uint32_t lo = (uint32_t)f2e4m3((x0.x - b0.x) * SCALE_X, (x0.y - b0.y) * SCALE_X)
                | ((uint32_t)f2e4m3((x0.z - b0.z) * SCALE_X, (x0.w - b0.w) * SCALE_X) << 16);
    uint32_t hi = (uint32_t)f2e4m3((x1.x - b1.x) * SCALE_X, (x1.y - b1.y) * SCALE_X)
                | ((uint32_t)f2e4m3((x1.z - b1.z) * SCALE_X, (x1.w - b1.w) * SCALE_X) << 16);
    *(uint2*)(g_x8 + i / 2) = make_uint2(lo, hi);
}

__global__ void conv_w_kernel(const float* __restrict__ w) {
    size_t i = ((size_t)blockIdx.x * 256 + threadIdx.x) * 8;
    if (i >= (size_t)N_LAT * D_IN) return;
    float4 x0 = *(const float4*)(w + i);
    float4 x1 = *(const float4*)(w + i + 4);
    uint32_t lo = (uint32_t)f2e4m3(x0.x * SCALE_W, x0.y * SCALE_W)
                | ((uint32_t)f2e4m3(x0.z * SCALE_W, x0.w * SCALE_W) << 16);
    uint32_t hi = (uint32_t)f2e4m3(x1.x * SCALE_W, x1.y * SCALE_W)
                | ((uint32_t)f2e4m3(x1.z * SCALE_W, x1.w * SCALE_W) << 16);
    *(uint2*)(g_w8 + i / 2) = make_uint2(lo, hi);
}

// ---------------- GEMM helpers ----------------
__device__ __forceinline__ void cp_async16(void* smem, const void* gmem) {
    uint32_t s = (uint32_t)__cvta_generic_to_shared(smem);
    asm volatile("cp.async.cg.shared.global [%0], [%1], 16;\n" :: "r"(s), "l"(gmem));
}
__device__ __forceinline__ void cp_commit() { asm volatile("cp.async.commit_group;\n"); }
__device__ __forceinline__ void cp_wait0()  { asm volatile("cp.async.wait_group 0;\n"); }

__device__ __forceinline__ void ldm_x4(uint32_t* r, const void* p) {
    uint32_t s = (uint32_t)__cvta_generic_to_shared(p);
    asm volatile("ldmatrix.sync.aligned.m8n8.x4.shared.b16 {%0,%1,%2,%3}, [%4];\n"
                 : "=r"(r[0]), "=r"(r[1]), "=r"(r[2]), "=r"(r[3]) : "r"(s));
}

// fp8 e4m3 MMA: m16n8k32, same fragment register shapes as m16n8k16.f16 with
// each 16-bit ldmatrix unit packing 2 consecutive-k e4m3 values.
__device__ __forceinline__ void mma_fp8(float* c, const uint32_t* a, uint32_t b0, uint32_t b1) {
    asm volatile("mma.sync.aligned.m16n8k32.row.col.f32.e4m3.e4m3.f32 "
                 "{%0,%1,%2,%3}, {%4,%5,%6,%7}, {%8,%9}, {%0,%1,%2,%3};\n"
                 : "+f"(c[0]), "+f"(c[1]), "+f"(c[2]), "+f"(c[3])
                 : "r"(a[0]), "r"(a[1]), "r"(a[2]), "r"(a[3]), "r"(b0), "r"(b1));
}

// pre = bf16( ((x-b_dec)*4 @ (W*32)^T)/128 + b_enc ), approx ranking only.
// CTA tile 128x128, BK=32 units (=64 fp8 k), 256 threads, warp tile 32x64.
#define SROW 40  // 32 units + 8 pad (80B rows)
#define GM_NKT (D2 / 32)   // 32 iterations
__global__ __launch_bounds__(256) void gemm_fp8_kernel(const float* __restrict__ b_enc) {
    const int bx = blockIdx.x;   // N tile (128 of them)
    const int by = blockIdx.y;   // M tile (64 of them)
    __shared__ uint16_t sA[2][128 * SROW];
    __shared__ uint16_t sB[2][128 * SROW];

    const int t = threadIdx.x;
    const int lane = t & 31, w = t >> 5;
    const int wm = w & 3, wn = w >> 2;

    float acc[2][8][4];
#pragma unroll
    for (int mi = 0; mi < 2; ++mi)
#pragma unroll
        for (int ni = 0; ni < 8; ++ni)
#pragma unroll
            for (int q = 0; q < 4; ++q) acc[mi][ni][q] = 0.f;

    const int r0c = t >> 2, q0c = t & 3;
    const int r1c = (t + 256) >> 2, q1c = (t + 256) & 3;
    const uint16_t* gA = g_x8 + (size_t)(by * 128) * D2;
    const uint16_t* gB = g_w8 + (size_t)(bx * 128) * D2;

    const int offA0 = (wm * 32 + 0  + (lane & 15)) * SROW + ((lane >> 4) << 3);
    const int offA1 = (wm * 32 + 16 + (lane & 15)) * SROW + ((lane >> 4) << 3);
    const int bg = lane >> 3, blr = lane & 7;
    const int offBrow = wn * 64 + ((bg >= 2) ? 8 : 0) + blr;
    const int offBcol = (bg & 1) << 3;

    {
        cp_async16(&sA[0][r0c * SROW + q0c * 8], gA + (size_t)r0c * D2 + q0c * 8);
        cp_async16(&sA[0][r1c * SROW + q1c * 8], gA + (size_t)r1c * D2 + q1c * 8);
        cp_async16(&sB[0][r0c * SROW + q0c * 8], gB + (size_t)r0c * D2 + q0c * 8);
        cp_async16(&sB[0][r1c * SROW + q1c * 8], gB + (size_t)r1c * D2 + q1c * 8);
        cp_commit();
        cp_wait0();
        __syncthreads();
    }

    for (int kt = 0; kt < GM_NKT; ++kt) {
        const int cur = kt & 1, nxt = cur ^ 1;
        if (kt < GM_NKT - 1) {
            const int k0 = (kt + 1) * 32;
            cp_async16(&sA[nxt][r0c * SROW + q0c * 8], gA + (size_t)r0c * D2 + k0 + q0c * 8);
            cp_async16(&sA[nxt][r1c * SROW + q1c * 8], gA + (size_t)r1c * D2 + k0 + q1c * 8);
            cp_async16(&sB[nxt][r0c * SROW + q0c * 8], gB + (size_t)r0c * D2 + k0 + q0c * 8);
            cp_async16(&sB[nxt][r1c * SROW + q1c * 8], gB + (size_t)r1c * D2 + k0 + q1c * 8);
            cp_commit();
        }
#pragma unroll
        for (int ks = 0; ks < 2; ++ks) {
            uint32_t af[2][4];
            ldm_x4(af[0], &sA[cur][offA0 + ks * 16]);
            ldm_x4(af[1], &sA[cur][offA1 + ks * 16]);
            uint32_t bfr[4][4];
#pragma unroll
            for (int p = 0; p < 4; ++p)
                ldm_x4(bfr[p], &sB[cur][(offBrow + p * 16) * SROW + ks * 16 + offBcol]);
#pragma unroll
            for (int mi = 0; mi < 2; ++mi)
#pragma unroll
                for (int p = 0; p < 4; ++p) {
                    mma_fp8(acc[mi][2 * p],     af[mi], bfr[p][0], bfr[p][1]);
                    mma_fp8(acc[mi][2 * p + 1], af[mi], bfr[p][2], bfr[p][3]);
                }
        }
        if (kt < GM_NKT - 1) {
            cp_wait0();
            __syncthreads();
        }
    }

    const int gid = lane >> 2, tid4 = lane & 3;
#pragma unroll
    for (int mi = 0; mi < 2; ++mi) {
#pragma unroll
        for (int ni = 0; ni < 8; ++ni) {
            int r0 = by * 128 + wm * 32 + mi * 16 + gid;
            int c  = bx * 128 + wn * 64 + ni * 8 + tid4 * 2;
            float be0 = b_enc[c], be1 = b_enc[c + 1];
            *(__nv_bfloat162*)(g_pre + (size_t)r0 * N_LAT + c) =
                __floats2bfloat162_rn(acc[mi][ni][0] * INV_SCALE + be0,
                                      acc[mi][ni][1] * INV_SCALE + be1);
            *(__nv_bfloat162*)(g_pre + (size_t)(r0 + 8) * N_LAT + c) =
                __floats2bfloat162_rn(acc[mi][ni][2] * INV_SCALE + be0,
                                      acc[mi][ni][3] * INV_SCALE + be1);
        }
    }
}

// ---------------- fused select + exact rescore + INVERTED hybrid boundary + decode ----------
__global__ __launch_bounds__(256) void srd_kernel(
    const float* __restrict__ x, const float* __restrict__ W_enc,
    const float* __restrict__ b_enc, const float* __restrict__ W_dec,
    const float* __restrict__ b_dec, float* __restrict__ out)
{
    const int row = blockIdx.x;
    const int t = threadIdx.x;
    const int lane = t & 31, wid = t >> 5;

    __shared__ int    shist[1024];
    __shared__ int    scoarse[128];
    __shared__ float  sx[D_IN];
    __shared__ int    scand[CAND_CAP];
    __shared__ double sval[CAND_CAP];
    __shared__ int    s_seli[K_TOP];
    __shared__ float  s_selv[K_TOP];
    __shared__ double s_seld[K_TOP];
    __shared__ int    scnt;
    __shared__ float  s_thr;
    __shared__ int    swin[WIN_CAP];
    __shared__ float  swinv[WIN_CAP];
    __shared__ double swind[WIN_CAP];
    __shared__ int    swincnt;

#pragma unroll
    for (int i = t; i < 1024; i += 256) shist[i] = 0;
#pragma unroll
    for (int i = t; i < D_IN; i += 256) sx[i] = x[(size_t)row * D_IN + i] - b_dec[i];
    if (t == 0) { scnt = 0; swincnt = 0; }
    __syncthreads();

    const uint4* p4 = (const uint4*)(g_pre + (size_t)row * N_LAT);

#pragma unroll
    for (int j = 0; j < 8; ++j) {
        uint4 v = p4[t + 256 * j];
        uint32_t ws[4] = {v.x, v.y, v.z, v.w};
#pragma unroll
        for (int wi = 0; wi < 4; ++wi) {
            uint32_t h0 = ws[wi] & 0xFFFFu, h1 = ws[wi] >> 16;
            if (h0 > 0x3F80u && h0 < 0x8000u) atomicAdd(&shist[h0 >> 5], 1);
            if (h1 > 0x3F80u && h1 < 0x8000u) atomicAdd(&shist[h1 >> 5], 1);
        }
    }
    __syncthreads();

    if (t < 128) {
        int cs = 0;
#pragma unroll
        for (int f = 0; f < 8; ++f) cs += shist[t * 8 + f];
        scoarse[t] = cs;
    }
    __syncthreads();
    if (t == 0) {
        int cum = 0, tb = 509;
        for (int c = 127; c >= 0; --c) {
            if (cum + scoarse[c] >= CAND_MIN) {
                for (int f = 7; f >= 0; --f) {
                    cum += shist[c * 8 + f];
                    if (cum >= CAND_MIN) { tb = c * 8 + f; break; }
                }
                break;
            }
            cum += scoarse[c];
        }
        __nv_bfloat16_raw er; er.x = (unsigned short)(tb << 5);
        float edge = __bfloat162float(*(__nv_bfloat16*)&er);
        float thr = edge - SEL_MARGIN;
        s_thr = (thr < 0.5f) ? 0.5f : thr;
    }
    __syncthreads();
    const float thr = s_thr;

#pragma unroll
    for (int j = 0; j < 8; ++j) {
        int idx = t + 256 * j;
        uint4 v = p4[idx];
        uint32_t ws[4] = {v.x, v.y, v.z, v.w};
#pragma unroll
        for (int wi = 0; wi < 4; ++wi) {
            uint32_t h0 = ws[wi] & 0xFFFFu, h1 = ws[wi] >> 16;
            if (h0 < 0x8000u) {
                __nv_bfloat16_raw r0b; r0b.x = (unsigned short)h0;
                if (__bfloat162float(*(__nv_bfloat16*)&r0b) >= thr) {
                    int pos = atomicAdd(&scnt, 1);
                    if (pos < CAND_CAP) scand[pos] = idx * 8 + wi * 2;
                }
            }
            if (h1 < 0x8000u) {
                __nv_bfloat16_raw r1b; r1b.x = (unsigned short)h1;
                if (__bfloat162float(*(__nv_bfloat16*)&r1b) >= thr) {
                    int pos = atomicAdd(&scnt, 1);
                    if (pos < CAND_CAP) scand[pos] = idx * 8 + wi * 2 + 1;
                }
            }
        }
    }
    __syncthreads();
    const int cnt = (scnt < CAND_CAP) ? scnt : CAND_CAP;

    const float4* sx4 = (const float4*)sx;
    for (int c = wid; c < cnt; c += 8) {
        const int jlat = scand[c];
        const float4* w4 = (const float4*)(W_enc + (size_t)jlat * D_IN);
        float s = 0.f, comp = 0.f;
#pragma unroll
        for (int i = 0; i < 16; ++i) {
            float4 wv = w4[lane + 32 * i];
            float4 xv = sx4[lane + 32 * i];
            float pr[4], er[4];
            pr[0] = wv.x * xv.x; er[0] = fmaf(wv.x, xv.x, -pr[0]);
            pr[1] = wv.y * xv.y; er[1] = fmaf(wv.y, xv.y, -pr[1]);
            pr[2] = wv.z * xv.z; er[2] = fmaf(wv.z, xv.z, -pr[2]);
            pr[3] = wv.w * xv.w; er[3] = fmaf(wv.w, xv.w, -pr[3]);
#pragma unroll
            for (int q = 0; q < 4; ++q) {
                float tt = s + pr[q];
                float z  = tt - s;
                comp += (s - (tt - z)) + (pr[q] - z) + er[q];
                s = tt;
            }
        }
#pragma unroll
        for (int o = 16; o; o >>= 1) {
            float s2 = __shfl_xor_sync(0xffffffffu, s, o);
            float c2 = __shfl_xor_sync(0xffffffffu, comp, o);
            float tt = s + s2;
            float z  = tt - s;
            comp = comp + c2 + (s - (tt - z)) + (s2 - z);
            s = tt;
        }
        if (lane == 0) sval[c] = (double)s + (double)comp + (double)b_enc[jlat];
    }
    __syncthreads();

    for (int c0 = t; c0 < cnt; c0 += 256) {
        double myv = sval[c0];
        int myj = scand[c0];
        int rank = 0;
        for (int c = 0; c < cnt; ++c) {
            double v = sval[c];
            if (v > myv || (v == myv && scand[c] < myj)) ++rank;
        }
        if (rank < K_TOP) { s_seli[rank] = myj; s_selv[rank] = (float)myv; s_seld[rank] = myv; }
    }
    __syncthreads();
    const int kmax = (cnt < K_TOP) ? cnt : K_TOP;

    if (kmax == K_TOP) {
        const double v32 = s_seld[K_TOP - 1];
        for (int c0 = t; c0 < cnt; c0 += 256) {
            double d = sval[c0] - v32;
            if (d <= WIN_EPS && d >= -WIN_EPS) {
                int p = atomicAdd(&swincnt, 1);
                if (p < WIN_CAP) { swin[p] = scand[c0]; swind[p] = sval[c0]; }
            }
        }
        __syncthreads();
        int wcnt = (swincnt < WIN_CAP) ? swincnt : WIN_CAP;
        if (wcnt >= 2) {
            if (t < wcnt) {
                const int j = swin[t];
                const float* wr = W_enc + (size_t)j * D_IN;
                float acc = 0.f;
                for (int k = 0; k < D_IN; ++k) acc = fmaf(wr[k], sx[k], acc);
                swinv[t] = acc + b_enc[j];
            }
            __syncthreads();
            if (t == 0) {
                int slots[WIN_CAP]; int m = 0;
                for (int k = 0; k < K_TOP; ++k) {
                    double d = s_seld[k] - v32;
                    if (d <= WIN_EPS && d >= -WIN_EPS && m < WIN_CAP) slots[m++] = k;
                }
                if (m > wcnt) m = wcnt;
                bool used[WIN_CAP];
                for (int c = 0; c < wcnt; ++c) used[c] = false;
                for (int r = 0; r < m; ++r) {
                    int best = -1;
                    for (int c = 0; c < wcnt; ++c) {
                        if (used[c]) continue;
                        if (best < 0) { best = c; continue; }
                        double de = swind[c] - swind[best];
                        double ade = (de < 0.0) ? -de : de;
                        bool better;
                        if (ade <= CMP_TAU) {
                            if (de > 0.0)       better = true;
                            else if (de < 0.0)  better = false;
                            else                better = (swin[c] < swin[best]);
                        } else {
                            if (swinv[c] != swinv[best]) better = (swinv[c] > swinv[best]);
                            else                         better = (swin[c] < swin[best]);
                        }
                        if (better) best = c;
                    }
                    used[best] = true;
                    s_seli[slots[r]] = swin[best];
                    s_selv[slots[r]] = swinv[best];
                }
            }
            __syncthreads();
        }
    }

    const float4* bd4 = (const float4*)b_dec;
    float4 a0 = bd4[t], a1 = bd4[t + 256];
    for (int k = 0; k < kmax; ++k) {
        const float v = s_selv[k];
        const float4* wd4 = (const float4*)(W_dec + (size_t)s_seli[k] * D_IN);
        float4 w0 = wd4[t], w1 = wd4[t + 256];
        a0.x += v * w0.x; a0.y += v * w0.y; a0.z += v * w0.z; a0.w += v * w0.w;
        a1.x += v * w1.x; a1.y += v * w1.y; a1.z += v * w1.z; a1.w += v * w1.w;
    }
    float4* o4 = (float4*)(out + (size_t)row * D_IN);
    o4[t] = a0;
    o4[t + 256] = a1;
}

// ---------------- launch ----------------
extern "C" void kernel_launch(void* const* d_in, const int* in_sizes, int n_in,
                              void* d_out, int out_size) {
    const float* x     = (const float*)d_in[0];
    const float* W_enc = (const float*)d_in[1];
    const float* b_enc = (const float*)d_in[2];
    const float* W_dec = (const float*)d_in[3];
    const float* b_dec = (const float*)d_in[4];
    float* out = (float*)d_out;

    conv_x_kernel<<<(B_TOK * D_IN / 8 + 255) / 256, 256>>>(x, b_dec);
    conv_w_kernel<<<(N_LAT * D_IN / 8 + 255) / 256, 256>>>(W_enc);
    gemm_fp8_kernel<<<dim3(N_LAT / 128, B_TOK / 128), 256>>>(b_enc);
    srd_kernel<<<B_TOK, 256>>>(x, W_enc, b_enc, W_dec, b_dec, out);
}